// round 17
// baseline (speedup 1.0000x reference)
#include <cuda_runtime.h>
#include <cuda_fp16.h>
#include <cstdint>

#define S_LEN 2048
#define E_DIM 1024
#define NH    16
#define HD    64
#define WWIN  128
#define BATCH 2
#define M_TOT (BATCH * S_LEN)   // 4096

// ---------------- scratch (device globals; no allocations allowed) ----------------
__device__ float g_Vtot[BATCH * NH * HD];
__device__ __half g_Xh16[M_TOT * E_DIM];
__device__ __half g_Wh16[3 * E_DIM * E_DIM];
__device__ __half g_Q16[M_TOT * E_DIM];
__device__ __half g_K16[M_TOT * E_DIM];
__device__ __half g_V16[M_TOT * E_DIM];

// ---------------- PTX helpers (baseline ISA only) ----------------
__device__ __forceinline__ uint32_t smem_u32(const void* p) {
    uint32_t a;
    asm("{ .reg .u64 t; cvta.to.shared.u64 t, %1; cvt.u32.u64 %0, t; }" : "=r"(a) : "l"(p));
    return a;
}
__device__ __forceinline__ void cp_async16(uint32_t s, const void* g) {
    asm volatile("cp.async.cg.shared.global [%0], [%1], 16;" :: "r"(s), "l"(g) : "memory");
}
#define CP_COMMIT() asm volatile("cp.async.commit_group;" ::: "memory")
#define CP_WAIT(n)  asm volatile("cp.async.wait_group %0;" :: "n"(n) : "memory")

__device__ __forceinline__ void ldmx4(uint32_t r[4], uint32_t addr) {
    asm volatile("ldmatrix.sync.aligned.m8n8.x4.shared.b16 {%0,%1,%2,%3}, [%4];"
                 : "=r"(r[0]), "=r"(r[1]), "=r"(r[2]), "=r"(r[3]) : "r"(addr));
}
__device__ __forceinline__ void ldmx4t(uint32_t r[4], uint32_t addr) {
    asm volatile("ldmatrix.sync.aligned.m8n8.x4.trans.shared.b16 {%0,%1,%2,%3}, [%4];"
                 : "=r"(r[0]), "=r"(r[1]), "=r"(r[2]), "=r"(r[3]) : "r"(addr));
}
__device__ __forceinline__ void mma16816h(float c[4], const uint32_t a[4],
                                          uint32_t b0, uint32_t b1) {
    asm volatile(
        "mma.sync.aligned.m16n8k16.row.col.f32.f16.f16.f32 "
        "{%0,%1,%2,%3}, {%4,%5,%6,%7}, {%8,%9}, {%0,%1,%2,%3};"
        : "+f"(c[0]), "+f"(c[1]), "+f"(c[2]), "+f"(c[3])
        : "r"(a[0]), "r"(a[1]), "r"(a[2]), "r"(a[3]), "r"(b0), "r"(b1));
}

// ============================================================================
// Kernel 0: merged fp32 -> f16 convert (2 float4 quads per thread) + zero Vtot.
// All region boundaries are even in quad units, so a (2i, 2i+1) pair never
// straddles tensors.
// ============================================================================
#define XQ (M_TOT * E_DIM / 4)      // 1048576
#define WQ (E_DIM * E_DIM / 4)      // 262144
#define SPLIT_BLOCKS ((XQ + 3 * WQ) / 512)   // 3584

__global__ __launch_bounds__(256, 8)
void split_all_kernel(const float* __restrict__ x, const float* __restrict__ wq,
                      const float* __restrict__ wk, const float* __restrict__ wv) {
    if (blockIdx.x == 0) {   // zero Vtot for this replay (epilogue accumulates)
#pragma unroll
        for (int k = 0; k < 8; k++) g_Vtot[threadIdx.x * 8 + k] = 0.f;
    }
    const int i = blockIdx.x * 256 + threadIdx.x;
    const int k0 = 2 * i;            // first quad of the pair
    const float* src;
    __half2* dst;
    int k;
    if (k0 < XQ) {
        src = x; k = k0; dst = (__half2*)g_Xh16;
    } else {
        const int j = k0 - XQ;
        const int w = j / WQ;
        k = j - w * WQ;
        src = (w == 0) ? wq : (w == 1) ? wk : wv;
        dst = (__half2*)(g_Wh16 + (size_t)w * E_DIM * E_DIM);
    }
    float4 v0 = ((const float4*)src)[k];
    float4 v1 = ((const float4*)src)[k + 1];
    dst[2 * k]     = __floats2half2_rn(v0.x, v0.y);
    dst[2 * k + 1] = __floats2half2_rn(v0.z, v0.w);
    dst[2 * k + 2] = __floats2half2_rn(v1.x, v1.y);
    dst[2 * k + 3] = __floats2half2_rn(v1.z, v1.w);
}

// ============================================================================
// Kernel 1: single-product f16 GEMM via mma.sync, 3-stage cp.async pipeline,
// ONE __syncthreads per K-chunk.  Out = X16 @ W16.T + b.
// Epilogue writes f16; V also reduces rounded outputs into g_Vtot.
// ============================================================================
#define KC 64
#define NCHUNK (E_DIM / KC)
#define RS 144
#define T_A 0
#define T_B 18432
#define STAGE 36864
#define NSTAGE 3
#define GEMM_SMEM (NSTAGE * STAGE)   // 110592 -> 2 CTAs/SM (221KB <= 228KB)

__device__ __forceinline__ void issue_chunk(uint32_t sdst, int kc, int m0, int n0,
                                            const __half* Wh, int tid) {
#pragma unroll
    for (int t4 = 0; t4 < 4; t4++) {
        const int idx = tid + t4 * 256;
        const int r = idx >> 3, c = idx & 7;
        const uint32_t so = (uint32_t)(r * RS + c * 16);
        cp_async16(sdst + T_A + so,
                   g_Xh16 + (size_t)(m0 + r) * E_DIM + kc * KC + c * 8);
        cp_async16(sdst + T_B + so,
                   Wh + (size_t)(n0 + r) * E_DIM + kc * KC + c * 8);
    }
}

__global__ __launch_bounds__(256, 2)
void hmma_gemm_kernel(const float* __restrict__ bq, const float* __restrict__ bk,
                      const float* __restrict__ bv) {
    extern __shared__ char dsm[];
    const uint32_t sbase = smem_u32(dsm);
    const int tid  = threadIdx.x;
    const int wid  = tid >> 5;
    const int lane = tid & 31;
    const int n0 = blockIdx.x * 128;
    const int m0 = blockIdx.y * 128;
    const int z  = blockIdx.z;

    const __half* Wh = g_Wh16 + (size_t)z * E_DIM * E_DIM;
    const float* bias = (z == 0) ? bq : (z == 1) ? bk : bv;

    const int wm = wid & 1;
    const int wn = wid >> 1;

    float acc[4][4][4];
#pragma unroll
    for (int mt = 0; mt < 4; mt++)
#pragma unroll
        for (int nt = 0; nt < 4; nt++)
#pragma unroll
            for (int j = 0; j < 4; j++) acc[mt][nt][j] = 0.f;

    const uint32_t laneOff = (uint32_t)((lane & 15) * RS + (lane >> 4) * 16);

    issue_chunk(sbase, 0, m0, n0, Wh, tid);
    CP_COMMIT();
    issue_chunk(sbase + STAGE, 1, m0, n0, Wh, tid);
    CP_COMMIT();

    int sidx = 0;   // stage index = c % 3
    for (int c = 0; c < NCHUNK; c++) {
        if (c + 1 < NCHUNK) { CP_WAIT(1); } else { CP_WAIT(0); }
        __syncthreads();
        if (c + 2 < NCHUNK) {
            int nidx = sidx + 2; if (nidx >= NSTAGE) nidx -= NSTAGE;
            issue_chunk(sbase + (uint32_t)nidx * STAGE, c + 2, m0, n0, Wh, tid);
            CP_COMMIT();
        }
        const uint32_t sbuf = sbase + (uint32_t)sidx * STAGE;
        const uint32_t sA = sbuf + T_A + (uint32_t)(wm * 64) * RS + laneOff;
        const uint32_t sB = sbuf + T_B + (uint32_t)(wn * 32) * RS + laneOff;
#pragma unroll
        for (int ks = 0; ks < 4; ks++) {
            uint32_t bfr[2][4];
#pragma unroll
            for (int p = 0; p < 2; p++)
                ldmx4(bfr[p], sB + (uint32_t)(p * 16) * RS + ks * 32);
#pragma unroll
            for (int mt = 0; mt < 4; mt++) {
                uint32_t a[4];
                ldmx4(a, sA + (uint32_t)(mt * 16) * RS + ks * 32);
#pragma unroll
                for (int nt = 0; nt < 4; nt++) {
                    const int p = nt >> 1, s = nt & 1;
                    mma16816h(acc[mt][nt], a, bfr[p][s], bfr[p][s + 2]);
                }
            }
        }
        if (++sidx >= NSTAGE) sidx = 0;
    }
    __syncthreads();   // protect smem before epilogue vred aliasing

    // epilogue: +bias, write f16; V also accumulates column sums (rounded vals)
    const int g   = lane >> 2;
    const int tig = lane & 3;
    __half* Oh = (z == 0) ? g_Q16 : (z == 1) ? g_K16 : g_V16;
    float vs0[4] = {0.f, 0.f, 0.f, 0.f};
    float vs1[4] = {0.f, 0.f, 0.f, 0.f};
#pragma unroll
    for (int mt = 0; mt < 4; mt++) {
        const int rbase = m0 + wm * 64 + mt * 16 + g;
#pragma unroll
        for (int nt = 0; nt < 4; nt++) {
            const int ncol = n0 + wn * 32 + nt * 8 + tig * 2;
            const float b0 = bias[ncol], b1 = bias[ncol + 1];
            __half2 r0 = __floats2half2_rn(acc[mt][nt][0] + b0, acc[mt][nt][1] + b1);
            __half2 r1 = __floats2half2_rn(acc[mt][nt][2] + b0, acc[mt][nt][3] + b1);
            *(__half2*)&Oh[(size_t)rbase * E_DIM + ncol] = r0;
            *(__half2*)&Oh[(size_t)(rbase + 8) * E_DIM + ncol] = r1;
            if (z == 2) {
                float2 f0 = __half22float2(r0), f1 = __half22float2(r1);
                vs0[nt] += f0.x + f1.x;
                vs1[nt] += f0.y + f1.y;
            }
        }
    }
    if (z == 2) {
        float* vred = (float*)dsm;
        if (tid < 64) vred[tid] = 0.f;
        __syncthreads();
        const int dbase = (wn & 1) * 32 + tig * 2;
#pragma unroll
        for (int nt = 0; nt < 4; nt++) {
            atomicAdd(&vred[dbase + nt * 8], vs0[nt]);
            atomicAdd(&vred[dbase + nt * 8 + 1], vs1[nt]);
        }
        __syncthreads();
        if (tid < 64) atomicAdd(&g_Vtot[(m0 >> 7) * 64 + tid], vred[tid]);
    }
}

// ============================================================================
// Kernel 2: tensor-core windowed attention, 4 query-tiles per CTA (unchanged).
// ============================================================================
#define TB 4
#define A_OFF_VT   0
#define A_OFF_DEN  256
#define A_OFF_RS   512
#define A_OFF_Q    1024
#define A_OFF_K    10240
#define A_OFF_V    56320
#define A_SMEM     102400
#define A_OFF_OP   A_OFF_K     // 8x16x64 f32 = 32KB partials alias K after sync

__device__ __forceinline__ uint32_t packh2(float a, float b) {
    __half2 h = __floats2half2_rn(a, b);
    return *(uint32_t*)&h;
}

__global__ __launch_bounds__(256, 2)
void attn_tc_kernel(float* __restrict__ out) {
    extern __shared__ char dsm[];
    const uint32_t sbase = smem_u32(dsm);
    const int t0  = blockIdx.x * TB;
    const int h   = blockIdx.y;
    const int b   = blockIdx.z;
    const int tid = threadIdx.x;
    const int wid = tid >> 5;
    const int lane = tid & 31;

    float* vt  = (float*)(dsm + A_OFF_VT);
    float* den = (float*)(dsm + A_OFF_DEN);
    float* rsp = (float*)(dsm + A_OFF_RS);

    const size_t headrow = (size_t)b * S_LEN + (size_t)h * 128;

    // ---- load phase: pure cp.async ----
#pragma unroll
    for (int qh = 0; qh < 2; qh++) {   // Q: 4 rows = 512 x 16B units
        const int u = qh * 256 + tid;
        const int qi = u >> 3, c = u & 7;   // qi 0..63
        cp_async16(sbase + A_OFF_Q + (uint32_t)(qi * 144 + c * 16),
                   g_Q16 + (headrow + t0 + (qi >> 4)) * E_DIM + (qi & 15) * 64 + c * 8);
    }
    if (tid < 64) vt[tid] = g_Vtot[((b * NH) + h) * HD + tid];

    const int r0 = t0 - 8;
#pragma unroll 5
    for (int rro = 0; rro < 20; rro++) {
        const int rr = r0 + rro;
        const bool ok = (rr >= 0 && rr < 128);
        const int half = tid >> 7;          // 0: K, 1: V
        const int jl16 = (tid >> 3) & 15, c = tid & 7;
        const uint32_t doff = (half ? A_OFF_V : A_OFF_K) +
                              (uint32_t)((rro * 16 + jl16) * 144 + c * 16);
        if (ok) {
            const __half* src = (half ? g_V16 : g_K16) +
                                (headrow + rr) * E_DIM + jl16 * 64 + c * 8;
            cp_async16(sbase + doff, src);
        } else {
            *(uint4*)(dsm + doff) = make_uint4(0, 0, 0, 0);
        }
    }
    CP_COMMIT();
    CP_WAIT(0);
    __syncthreads();

    // ---- per-warp: QK mma -> exp/mask -> P frags -> PV mma ----
    const int tile  = wid >> 1;      // 0..3
    const int wslot = wid & 1;       // 0..1
    const int g     = lane >> 2;
    const int tig   = lane & 3;
    const uint32_t loL = sbase + (uint32_t)((lane & 15) * 144 + (lane >> 4) * 16);
    const int i0 = (t0 + tile) * 16 + g, i1 = i0 + 8;

    // hoist Q fragments for this warp's tile
    uint32_t qa[4][4];
#pragma unroll
    for (int ks = 0; ks < 4; ks++)
        ldmx4(qa[ks], loL + A_OFF_Q + (uint32_t)tile * 2304 + ks * 32);

    float oacc[8][4];
#pragma unroll
    for (int dt = 0; dt < 8; dt++)
#pragma unroll
        for (int j = 0; j < 4; j++) oacc[dt][j] = 0.f;
    float rs0 = 0.f, rs1 = 0.f;

    for (int pr = wslot; pr < 17; pr += 2) {
        const uint32_t kvOff = (uint32_t)(tile + pr) * 2304;
        const int jgb = (r0 + tile + pr) * 16;
        float c0[4] = {0.f, 0.f, 0.f, 0.f};
        float c1[4] = {0.f, 0.f, 0.f, 0.f};
#pragma unroll
        for (int ks = 0; ks < 4; ks++) {
            uint32_t kh[4];
            ldmx4(kh, loL + A_OFF_K + kvOff + ks * 32);
            mma16816h(c0, qa[ks], kh[0], kh[2]);
            mma16816h(c1, qa[ks], kh[1], kh[3]);
        }
        uint32_t pf[4];
#pragma unroll
        for (int s = 0; s < 2; s++) {
            const float* cc = s ? c1 : c0;
            const int jg0 = jgb + s * 8 + 2 * tig;
            const int jg1 = jg0 + 1;
            const bool ok0 = (jg0 >= 0) && (jg0 < S_LEN);
            const bool ok1 = (jg1 >= 0) && (jg1 < S_LEN);
            float w00 = (ok0 && jg0 >= i0 - WWIN && jg0 < i0 + WWIN)
                        ? (__expf(cc[0] * 0.125f) - 1.f) : 0.f;
            float w01 = (ok1 && jg1 >= i0 - WWIN && jg1 < i0 + WWIN)
                        ? (__expf(cc[1] * 0.125f) - 1.f) : 0.f;
            float w10 = (ok0 && jg0 >= i1 - WWIN && jg0 < i1 + WWIN)
                        ? (__expf(cc[2] * 0.125f) - 1.f) : 0.f;
            float w11 = (ok1 && jg1 >= i1 - WWIN && jg1 < i1 + WWIN)
                        ? (__expf(cc[3] * 0.125f) - 1.f) : 0.f;
            rs0 += w00 + w01;
            rs1 += w10 + w11;
            pf[s * 2 + 0] = packh2(w00, w01);
            pf[s * 2 + 1] = packh2(w10, w11);
        }
#pragma unroll
        for (int dp = 0; dp < 4; dp++) {
            uint32_t vb[4];
            ldmx4t(vb, loL + A_OFF_V + kvOff + dp * 32);
            mma16816h(oacc[dp * 2 + 0], pf, vb[0], vb[1]);
            mma16816h(oacc[dp * 2 + 1], pf, vb[2], vb[3]);
        }
    }

    rs0 += __shfl_xor_sync(0xFFFFFFFF, rs0, 1);
    rs0 += __shfl_xor_sync(0xFFFFFFFF, rs0, 2);
    rs1 += __shfl_xor_sync(0xFFFFFFFF, rs1, 1);
    rs1 += __shfl_xor_sync(0xFFFFFFFF, rs1, 2);
    if (tig == 0) {
        rsp[tile * 32 + wslot * 16 + g]     = rs0;
        rsp[tile * 32 + wslot * 16 + g + 8] = rs1;
    }
    __syncthreads();   // all K/V reads done; op may alias K now

    {
        float* op = (float*)(dsm + A_OFF_OP) + wid * 1024;
#pragma unroll
        for (int dt = 0; dt < 8; dt++) {
            *(float2*)&op[g * 64 + dt * 8 + 2 * tig] =
                make_float2(oacc[dt][0], oacc[dt][1]);
            *(float2*)&op[(g + 8) * 64 + dt * 8 + 2 * tig] =
                make_float2(oacc[dt][2], oacc[dt][3]);
        }
    }
    if (tid < 64) {   // 64 queries
        const int tv = tid >> 4, qr = tid & 15;
        den[tid] = (float)S_LEN + rsp[tv * 32 + qr] + rsp[tv * 32 + 16 + qr];
    }
    __syncthreads();

#pragma unroll
    for (int halfq = 0; halfq < 2; halfq++) {
        const int qv = halfq * 32 + (tid >> 3);   // 0..63
        const int d0 = (tid & 7) * 8;
        const int tv = qv >> 4, qr = qv & 15;
        const float* opf = (const float*)(dsm + A_OFF_OP);
        float4 s0 = *(const float4*)&vt[d0];
        float4 s1 = *(const float4*)&vt[d0 + 4];
#pragma unroll
        for (int w2 = 0; w2 < 2; w2++) {
            const float* op = &opf[((tv * 2 + w2) * 16 + qr) * 64];
            const float4 a0 = *(const float4*)&op[d0];
            const float4 a1 = *(const float4*)&op[d0 + 4];
            s0.x += a0.x; s0.y += a0.y; s0.z += a0.z; s0.w += a0.w;
            s1.x += a1.x; s1.y += a1.y; s1.z += a1.z; s1.w += a1.w;
        }
        const float inv = 1.0f / den[qv];
        s0.x *= inv; s0.y *= inv; s0.z *= inv; s0.w *= inv;
        s1.x *= inv; s1.y *= inv; s1.z *= inv; s1.w *= inv;
        const int i = (t0 + tv) * 16 + qr;
        float* orow = &out[((size_t)b * S_LEN + i) * E_DIM + h * HD + d0];
        *(float4*)orow = s0;
        *(float4*)(orow + 4) = s1;
    }
}

// ============================================================================
// kernel_launch
// ============================================================================
extern "C" void kernel_launch(void* const* d_in, const int* in_sizes, int n_in,
                              void* d_out, int out_size) {
    (void)in_sizes; (void)n_in; (void)out_size;
    const float* x  = (const float*)d_in[0];
    const float* Wq = (const float*)d_in[1];
    const float* bq = (const float*)d_in[2];
    const float* Wk = (const float*)d_in[3];
    const float* bk = (const float*)d_in[4];
    const float* Wv = (const float*)d_in[5];
    const float* bv = (const float*)d_in[6];
    float* out = (float*)d_out;

    split_all_kernel<<<SPLIT_BLOCKS, 256>>>(x, Wq, Wk, Wv);

    cudaFuncSetAttribute(hmma_gemm_kernel, cudaFuncAttributeMaxDynamicSharedMemorySize,
                         GEMM_SMEM);
    dim3 gg(E_DIM / 128, M_TOT / 128, 3);
    hmma_gemm_kernel<<<gg, 256, GEMM_SMEM>>>(bq, bk, bv);

    cudaFuncSetAttribute(attn_tc_kernel, cudaFuncAttributeMaxDynamicSharedMemorySize,
                         A_SMEM);
    dim3 g3(S_LEN / (16 * TB), NH, BATCH);   // (32, 16, 2)
    attn_tc_kernel<<<g3, 256, A_SMEM>>>(out);
}